// round 8
// baseline (speedup 1.0000x reference)
#include <cuda_runtime.h>
#include <cstdint>

// ---------------- problem constants ----------------
#define B_WIN    4096
#define SEQ      49
#define CDIM     192
#define NHEAD    6
#define HDIM     32
#define KD       192
#define QKV_COLS 576
#define MROWS    200704       // B_WIN * SEQ

// ---------------- scratch (__device__ globals, allocation-free) -------------
__device__ float g_qkv [(size_t)B_WIN * SEQ * QKV_COLS];
__device__ float g_attn[(size_t)B_WIN * SEQ * CDIM];
__device__ float g_bm  [64 * NHEAD * SEQ * 56];   // fused bias+mask, cols padded to 56

__device__ __forceinline__ uint32_t f2tf32(float x) {
    uint32_t r; asm("cvt.rna.tf32.f32 %0, %1;" : "=r"(r) : "f"(x)); return r;
}
__device__ __forceinline__ void split2(float v, float& hi, float& lo) {
    hi = __uint_as_float(f2tf32(v));
    lo = __uint_as_float(f2tf32(v - hi));
}

__device__ __forceinline__ void mma_tf32(float* d, const uint32_t* a, const uint32_t* b) {
    asm volatile(
        "mma.sync.aligned.m16n8k8.row.col.f32.tf32.tf32.f32 "
        "{%0,%1,%2,%3}, {%4,%5,%6,%7}, {%8,%9}, {%0,%1,%2,%3};"
        : "+f"(d[0]), "+f"(d[1]), "+f"(d[2]), "+f"(d[3])
        : "r"(a[0]), "r"(a[1]), "r"(a[2]), "r"(a[3]), "r"(b[0]), "r"(b[1]));
}
__device__ __forceinline__ void mma_f(float* d, float a0, float a1, float a2, float a3,
                                      float b0, float b1) {
    asm volatile(
        "mma.sync.aligned.m16n8k8.row.col.f32.tf32.tf32.f32 "
        "{%0,%1,%2,%3}, {%4,%5,%6,%7}, {%8,%9}, {%0,%1,%2,%3};"
        : "+f"(d[0]), "+f"(d[1]), "+f"(d[2]), "+f"(d[3])
        : "r"(__float_as_uint(a0)), "r"(__float_as_uint(a1)),
          "r"(__float_as_uint(a2)), "r"(__float_as_uint(a3)),
          "r"(__float_as_uint(b0)), "r"(__float_as_uint(b1)));
}

// ---------------------------------------------------------------------------
// K0: fused bias+mask table: g_bm[w][h][n][m] (m padded to 56 with -1e30)
// ---------------------------------------------------------------------------
__global__ void bm_kernel(const float* __restrict__ table,
                          const float* __restrict__ mask,
                          const int* __restrict__ rel_index)
{
    int i = blockIdx.x * blockDim.x + threadIdx.x;
    if (i >= 64 * NHEAD * SEQ * 56) return;
    int m = i % 56; int t = i / 56;
    int n = t % SEQ; t /= SEQ;
    int h = t % NHEAD; int w = t / NHEAD;
    float v = -1e30f;
    if (m < SEQ)
        v = table[rel_index[n * SEQ + m] * NHEAD + h]
          + mask[((size_t)w * SEQ + n) * SEQ + m];
    g_bm[i] = v;
}

// ---------------------------------------------------------------------------
// tf32 HMMA GEMM: out[m][n] = sum_k A[m][k]*W[n][k] + bias[n]
//   Tile 128x96, BK=32, 256 thr = 8 warps (4M x 2N), warp tile 32x48.
//   TRIPLE-buffered SMEM, prefetch distance 2: LDG(kt+2) issued before
//   compute(kt); STS lands in buf (kt+2)%3 (== (kt-1)%3, freed last iter).
//   GRID: blockIdx.x = N-tile (fast) so A-tile sharers are co-resident (L2).
//   PHASE1: A = x, O = g_qkv (scale q cols: n0 < 192). !PHASE1: A=g_attn, O=Oin.
// ---------------------------------------------------------------------------
#define ABUF 4608u             // 128*36 floats
#define BBUF 3456u             // 96*36 floats
#define GEMM_SMEM_FLOATS (3u*(ABUF + BBUF))    // 24192 floats = 96768 B

template<bool PHASE1>
__global__ void __launch_bounds__(256, 2)
gemm_mma(const float* __restrict__ Ain, const float* __restrict__ W,
         const float* __restrict__ bias, float* __restrict__ Oin,
         int Ncols, float qscale)
{
    extern __shared__ float sm[];
    float* As[3] = { sm, sm + (ABUF + BBUF), sm + 2 * (ABUF + BBUF) };
    float* Bs[3] = { As[0] + ABUF, As[1] + ABUF, As[2] + ABUF };
    __shared__ float bias_s[96];

    const float* A = PHASE1 ? Ain : g_attn;
    float*       O = PHASE1 ? g_qkv : Oin;

    const int tid  = threadIdx.x;
    const int wid  = tid >> 5;
    const int lane = tid & 31;
    const int gid  = lane >> 2;
    const int tig  = lane & 3;
    const size_t m0 = (size_t)blockIdx.y * 128;   // M-tile: slow-varying
    const int    n0 = blockIdx.x * 96;            // N-tile: fast-varying
    const int    wm = (wid >> 1) * 32;
    const int    wn = (wid & 1) * 48;

    if (tid < 24) ((float4*)bias_s)[tid] = ((const float4*)(bias + n0))[tid];

    float4 pa[4], pb[3];

    auto ldg_tile = [&](int kt) {
        const int k0 = kt * 32;
        #pragma unroll
        for (int i = 0; i < 4; ++i) {
            int idx = tid + i * 256;
            int r = idx >> 3, q = idx & 7;
            pa[i] = *(const float4*)(A + (m0 + r) * (size_t)KD + k0 + q * 4);
        }
        #pragma unroll
        for (int i = 0; i < 3; ++i) {
            int idx = tid + i * 256;
            int r = idx >> 3, q = idx & 7;
            pb[i] = *(const float4*)(W + (size_t)(n0 + r) * KD + k0 + q * 4);
        }
    };
    auto sts_tile = [&](int buf) {
        #pragma unroll
        for (int i = 0; i < 4; ++i) {
            int idx = tid + i * 256;
            int r = idx >> 3, q = idx & 7;
            uint4 t = make_uint4(f2tf32(pa[i].x), f2tf32(pa[i].y),
                                 f2tf32(pa[i].z), f2tf32(pa[i].w));
            *(uint4*)(As[buf] + r * 36 + q * 4) = t;
        }
        #pragma unroll
        for (int i = 0; i < 3; ++i) {
            int idx = tid + i * 256;
            int r = idx >> 3, q = idx & 7;
            uint4 t = make_uint4(f2tf32(pb[i].x), f2tf32(pb[i].y),
                                 f2tf32(pb[i].z), f2tf32(pb[i].w));
            *(uint4*)(Bs[buf] + r * 36 + q * 4) = t;
        }
    };

    float acc[2][6][4] = {};

    // prologue: fill buffers 0 and 1
    ldg_tile(0);
    sts_tile(0);
    ldg_tile(1);
    sts_tile(1);
    __syncthreads();

    #pragma unroll 1
    for (int kt = 0; kt < 6; ++kt) {
        const int buf = kt % 3;
        if (kt < 4) ldg_tile(kt + 2);        // prefetch distance 2

        const uint32_t* Au = (const uint32_t*)As[buf];
        const uint32_t* Bu = (const uint32_t*)Bs[buf];
        #pragma unroll
        for (int kk = 0; kk < 32; kk += 8) {
            uint32_t afr[2][4], bfr[6][2];
            #pragma unroll
            for (int mi = 0; mi < 2; ++mi) {
                int r = wm + mi * 16 + gid;
                afr[mi][0] = Au[r * 36 + kk + tig];
                afr[mi][1] = Au[(r + 8) * 36 + kk + tig];
                afr[mi][2] = Au[r * 36 + kk + 4 + tig];
                afr[mi][3] = Au[(r + 8) * 36 + kk + 4 + tig];
            }
            #pragma unroll
            for (int ni = 0; ni < 6; ++ni) {
                int r = wn + ni * 8 + gid;
                bfr[ni][0] = Bu[r * 36 + kk + tig];
                bfr[ni][1] = Bu[r * 36 + kk + 4 + tig];
            }
            #pragma unroll
            for (int mi = 0; mi < 2; ++mi)
                #pragma unroll
                for (int ni = 0; ni < 6; ++ni)
                    mma_tf32(acc[mi][ni], afr[mi], bfr[ni]);
        }
        if (kt < 4) sts_tile((kt + 2) % 3);  // buf (kt-1)%3, freed last iter
        __syncthreads();
    }

    // ---- epilogue: stage to SMEM (stride 100), then coalesced STG ----
    float* stage = sm;
    #pragma unroll
    for (int mi = 0; mi < 2; ++mi) {
        int row0 = wm + mi * 16 + gid;
        #pragma unroll
        for (int ni = 0; ni < 6; ++ni) {
            int col0 = wn + ni * 8 + 2 * tig;
            *(float2*)(stage + row0 * 100 + col0)       = make_float2(acc[mi][ni][0], acc[mi][ni][1]);
            *(float2*)(stage + (row0 + 8) * 100 + col0) = make_float2(acc[mi][ni][2], acc[mi][ni][3]);
        }
    }
    __syncthreads();

    const bool doscale = PHASE1 && (n0 < CDIM);
    #pragma unroll
    for (int i = 0; i < 12; ++i) {
        int idx = tid + i * 256;
        int row = idx / 24, c4 = idx - row * 24;
        float4 v  = *(float4*)(stage + row * 100 + c4 * 4);
        float4 bv = *(float4*)(bias_s + c4 * 4);
        float4 o;
        o.x = v.x + bv.x; o.y = v.y + bv.y; o.z = v.z + bv.z; o.w = v.w + bv.w;
        if (doscale) { o.x *= qscale; o.y *= qscale; o.z *= qscale; o.w *= qscale; }
        *(float4*)(O + (m0 + row) * (size_t)Ncols + n0 + c4 * 4) = o;
    }
}

// ---------------------------------------------------------------------------
// K2: tensor-core attention. One block per (window, head), 128 thr / 4 warps.
// Warp w owns rows [w*16, w*16+16). 3xTF32 split MMAs for QK^T and P@V.
// Softmax in registers via quad shuffles; P fragments via intra-quad shfl.
// ---------------------------------------------------------------------------
#define QSTR 36
#define KSTR 36
#define VSTR 40
#define ATTN_SMEM_FLOATS (2*49*QSTR + 2*56*KSTR + 2*56*VSTR)   // 12040 -> 48160 B

__global__ void __launch_bounds__(128)
attn_mma()
{
    extern __shared__ float s[];
    float* qh = s;
    float* ql = qh + 49 * QSTR;
    float* kh = ql + 49 * QSTR;
    float* kl = kh + 56 * KSTR;
    float* vh = kl + 56 * KSTR;
    float* vl = vh + 56 * VSTR;

    const int b = blockIdx.x;
    const int h = blockIdx.y;
    const int tid = threadIdx.x;
    const float* base = g_qkv + (size_t)b * SEQ * QKV_COLS;

    for (int i = tid; i < 49 * 8; i += 128) {
        int n = i >> 3, c = (i & 7) * 4;
        float4 v = *(const float4*)(base + n * QKV_COLS + h * HDIM + c);
        float4 hi, lo;
        split2(v.x, hi.x, lo.x); split2(v.y, hi.y, lo.y);
        split2(v.z, hi.z, lo.z); split2(v.w, hi.w, lo.w);
        *(float4*)(qh + n * QSTR + c) = hi;
        *(float4*)(ql + n * QSTR + c) = lo;
    }
    for (int i = tid; i < 56 * 8; i += 128) {
        int n = i >> 3, c = (i & 7) * 4;
        float4 kv = make_float4(0.f, 0.f, 0.f, 0.f), vv = kv;
        if (n < SEQ) {
            const float* src = base + n * QKV_COLS + CDIM + h * HDIM + c;
            kv = *(const float4*)src;
            vv = *(const float4*)(src + CDIM);
        }
        float4 hi, lo;
        split2(kv.x, hi.x, lo.x); split2(kv.y, hi.y, lo.y);
        split2(kv.z, hi.z, lo.z); split2(kv.w, hi.w, lo.w);
        *(float4*)(kh + n * KSTR + c) = hi;
        *(float4*)(kl + n * KSTR + c) = lo;
        split2(vv.x, hi.x, lo.x); split2(vv.y, hi.y, lo.y);
        split2(vv.z, hi.z, lo.z); split2(vv.w, hi.w, lo.w);
        *(float4*)(vh + n * VSTR + c) = hi;
        *(float4*)(vl + n * VSTR + c) = lo;
    }
    __syncthreads();

    const int lane = tid & 31, w = tid >> 5;
    const int gid = lane >> 2, tig = lane & 3;
    const int row0 = w * 16 + gid, row1 = row0 + 8;
    const int r0c = min(row0, 48), r1c = min(row1, 48);

    float c[7][4] = {};
    #pragma unroll
    for (int ks = 0; ks < 4; ++ks) {
        const int dk = ks * 8;
        float a0h = qh[r0c * QSTR + dk + tig],     a0l = ql[r0c * QSTR + dk + tig];
        float a1h = qh[r1c * QSTR + dk + tig],     a1l = ql[r1c * QSTR + dk + tig];
        float a2h = qh[r0c * QSTR + dk + tig + 4], a2l = ql[r0c * QSTR + dk + tig + 4];
        float a3h = qh[r1c * QSTR + dk + tig + 4], a3l = ql[r1c * QSTR + dk + tig + 4];
        #pragma unroll
        for (int nt = 0; nt < 7; ++nt) {
            int kr = nt * 8 + gid;
            float b0h = kh[kr * KSTR + dk + tig],     b0l = kl[kr * KSTR + dk + tig];
            float b1h = kh[kr * KSTR + dk + tig + 4], b1l = kl[kr * KSTR + dk + tig + 4];
            mma_f(c[nt], a0h, a1h, a2h, a3h, b0h, b1h);
            mma_f(c[nt], a0h, a1h, a2h, a3h, b0l, b1l);
            mma_f(c[nt], a0l, a1l, a2l, a3l, b0h, b1h);
        }
    }

    const float* bmp = g_bm + ((size_t)((b & 63) * NHEAD + h)) * (SEQ * 56);
    #pragma unroll
    for (int nt = 0; nt < 7; ++nt) {
        float2 bm0 = *(const float2*)(bmp + r0c * 56 + nt * 8 + 2 * tig);
        float2 bm1 = *(const float2*)(bmp + r1c * 56 + nt * 8 + 2 * tig);
        c[nt][0] += bm0.x; c[nt][1] += bm0.y;
        c[nt][2] += bm1.x; c[nt][3] += bm1.y;
    }

    float mx0 = -1e30f, mx1 = -1e30f;
    #pragma unroll
    for (int nt = 0; nt < 7; ++nt) {
        mx0 = fmaxf(mx0, fmaxf(c[nt][0], c[nt][1]));
        mx1 = fmaxf(mx1, fmaxf(c[nt][2], c[nt][3]));
    }
    mx0 = fmaxf(mx0, __shfl_xor_sync(0xffffffffu, mx0, 1));
    mx0 = fmaxf(mx0, __shfl_xor_sync(0xffffffffu, mx0, 2));
    mx1 = fmaxf(mx1, __shfl_xor_sync(0xffffffffu, mx1, 1));
    mx1 = fmaxf(mx1, __shfl_xor_sync(0xffffffffu, mx1, 2));

    float s0 = 0.f, s1 = 0.f;
    #pragma unroll
    for (int nt = 0; nt < 7; ++nt) {
        c[nt][0] = __expf(c[nt][0] - mx0); s0 += c[nt][0];
        c[nt][1] = __expf(c[nt][1] - mx0); s0 += c[nt][1];
        c[nt][2] = __expf(c[nt][2] - mx1); s1 += c[nt][2];
        c[nt][3] = __expf(c[nt][3] - mx1); s1 += c[nt][3];
    }
    s0 += __shfl_xor_sync(0xffffffffu, s0, 1);
    s0 += __shfl_xor_sync(0xffffffffu, s0, 2);
    s1 += __shfl_xor_sync(0xffffffffu, s1, 1);
    s1 += __shfl_xor_sync(0xffffffffu, s1, 2);
    const float inv0 = 1.0f / s0, inv1 = 1.0f / s1;

    float o[4][4] = {};
    const int sA = (lane & ~3) | (tig >> 1);
    const int sB = sA + 2;
    const bool odd = tig & 1;
    #pragma unroll
    for (int j = 0; j < 7; ++j) {
        float t00 = __shfl_sync(0xffffffffu, c[j][0], sA);
        float t01 = __shfl_sync(0xffffffffu, c[j][1], sA);
        float t20 = __shfl_sync(0xffffffffu, c[j][0], sB);
        float t21 = __shfl_sync(0xffffffffu, c[j][1], sB);
        float t10 = __shfl_sync(0xffffffffu, c[j][2], sA);
        float t11 = __shfl_sync(0xffffffffu, c[j][3], sA);
        float t30 = __shfl_sync(0xffffffffu, c[j][2], sB);
        float t31 = __shfl_sync(0xffffffffu, c[j][3], sB);
        float a0 = odd ? t01 : t00;
        float a2 = odd ? t21 : t20;
        float a1 = odd ? t11 : t10;
        float a3 = odd ? t31 : t30;
        float a0h, a0l, a1h, a1l, a2h, a2l, a3h, a3l;
        split2(a0, a0h, a0l); split2(a1, a1h, a1l);
        split2(a2, a2h, a2l); split2(a3, a3h, a3l);
        const int vr0 = j * 8 + tig, vr1 = vr0 + 4;
        #pragma unroll
        for (int nd = 0; nd < 4; ++nd) {
            int col = nd * 8 + gid;
            float b0h = vh[vr0 * VSTR + col], b0l = vl[vr0 * VSTR + col];
            float b1h = vh[vr1 * VSTR + col], b1l = vl[vr1 * VSTR + col];
            mma_f(o[nd], a0h, a1h, a2h, a3h, b0h, b1h);
            mma_f(o[nd], a0h, a1h, a2h, a3h, b0l, b1l);
            mma_f(o[nd], a0l, a1l, a2l, a3l, b0h, b1h);
        }
    }

    float* ob = g_attn + (size_t)b * SEQ * CDIM + h * HDIM;
    if (row0 < SEQ) {
        #pragma unroll
        for (int nd = 0; nd < 4; ++nd)
            *(float2*)(ob + row0 * CDIM + nd * 8 + 2 * tig) =
                make_float2(o[nd][0] * inv0, o[nd][1] * inv0);
    }
    if (row1 < SEQ) {
        #pragma unroll
        for (int nd = 0; nd < 4; ++nd)
            *(float2*)(ob + row1 * CDIM + nd * 8 + 2 * tig) =
                make_float2(o[nd][2] * inv1, o[nd][3] * inv1);
    }
}

// ---------------------------------------------------------------------------
extern "C" void kernel_launch(void* const* d_in, const int* in_sizes, int n_in,
                              void* d_out, int out_size)
{
    const float* x     = (const float*)d_in[0];
    const float* mask  = (const float*)d_in[1];
    const float* table = (const float*)d_in[2];
    const float* qkvw  = (const float*)d_in[3];
    const float* qkvb  = (const float*)d_in[4];
    const float* projw = (const float*)d_in[5];
    const float* projb = (const float*)d_in[6];
    const int*   relix = (const int*)d_in[7];
    float* out = (float*)d_out;

    const float qscale = 0.17677669529663687f;  // 1/sqrt(32)
    const int gemm_smem = GEMM_SMEM_FLOATS * 4;
    const int attn_smem = ATTN_SMEM_FLOATS * 4;

    cudaFuncSetAttribute((void*)gemm_mma<true>,
                         cudaFuncAttributeMaxDynamicSharedMemorySize, gemm_smem);
    cudaFuncSetAttribute((void*)gemm_mma<false>,
                         cudaFuncAttributeMaxDynamicSharedMemorySize, gemm_smem);
    cudaFuncSetAttribute((void*)attn_mma,
                         cudaFuncAttributeMaxDynamicSharedMemorySize, attn_smem);

    bm_kernel<<<(64 * NHEAD * SEQ * 56 + 255) / 256, 256>>>(table, mask, relix);

    // QKV: M=200704, N=576. N-tile fast-varying -> A-tile sharers co-resident.
    gemm_mma<true><<<dim3(6, MROWS / 128), 256, gemm_smem>>>(
        x, qkvw, qkvb, nullptr, QKV_COLS, qscale);

    attn_mma<<<dim3(B_WIN, NHEAD), 128, attn_smem>>>();

    // Proj: M=200704, N=192. Same N-fast ordering.
    gemm_mma<false><<<dim3(2, MROWS / 128), 256, gemm_smem>>>(
        nullptr, projw, projb, out, CDIM, 1.0f);
}

// round 9
// speedup vs baseline: 1.1709x; 1.1709x over previous
#include <cuda_runtime.h>
#include <cstdint>

// ---------------- problem constants ----------------
#define B_WIN    4096
#define SEQ      49
#define CDIM     192
#define NHEAD    6
#define HDIM     32
#define KD       192
#define QKV_COLS 576
#define MROWS    200704       // B_WIN * SEQ

// ---------------- scratch (__device__ globals, allocation-free) -------------
__device__ float g_qkv [(size_t)B_WIN * SEQ * QKV_COLS];
__device__ float g_attn[(size_t)B_WIN * SEQ * CDIM];
__device__ float g_bm  [64 * NHEAD * SEQ * 56];   // fused bias+mask, cols padded to 56

__device__ __forceinline__ uint32_t f2tf32(float x) {
    uint32_t r; asm("cvt.rna.tf32.f32 %0, %1;" : "=r"(r) : "f"(x)); return r;
}
__device__ __forceinline__ void split2(float v, float& hi, float& lo) {
    hi = __uint_as_float(f2tf32(v));
    lo = __uint_as_float(f2tf32(v - hi));
}

__device__ __forceinline__ void mma_tf32(float* d, const uint32_t* a, const uint32_t* b) {
    asm volatile(
        "mma.sync.aligned.m16n8k8.row.col.f32.tf32.tf32.f32 "
        "{%0,%1,%2,%3}, {%4,%5,%6,%7}, {%8,%9}, {%0,%1,%2,%3};"
        : "+f"(d[0]), "+f"(d[1]), "+f"(d[2]), "+f"(d[3])
        : "r"(a[0]), "r"(a[1]), "r"(a[2]), "r"(a[3]), "r"(b[0]), "r"(b[1]));
}
__device__ __forceinline__ void mma_f(float* d, float a0, float a1, float a2, float a3,
                                      float b0, float b1) {
    asm volatile(
        "mma.sync.aligned.m16n8k8.row.col.f32.tf32.tf32.f32 "
        "{%0,%1,%2,%3}, {%4,%5,%6,%7}, {%8,%9}, {%0,%1,%2,%3};"
        : "+f"(d[0]), "+f"(d[1]), "+f"(d[2]), "+f"(d[3])
        : "r"(__float_as_uint(a0)), "r"(__float_as_uint(a1)),
          "r"(__float_as_uint(a2)), "r"(__float_as_uint(a3)),
          "r"(__float_as_uint(b0)), "r"(__float_as_uint(b1)));
}

__device__ __forceinline__ void cp16(uint32_t smem_addr, const void* gptr) {
    asm volatile("cp.async.cg.shared.global [%0], [%1], 16;"
                 :: "r"(smem_addr), "l"(gptr) : "memory");
}
#define CP_COMMIT() asm volatile("cp.async.commit_group;" ::: "memory")
#define CP_WAIT(n)  asm volatile("cp.async.wait_group %0;" :: "n"(n) : "memory")

// ---------------------------------------------------------------------------
// K0: fused bias+mask table: g_bm[w][h][n][m] (m padded to 56 with -1e30)
// ---------------------------------------------------------------------------
__global__ void bm_kernel(const float* __restrict__ table,
                          const float* __restrict__ mask,
                          const int* __restrict__ rel_index)
{
    int i = blockIdx.x * blockDim.x + threadIdx.x;
    if (i >= 64 * NHEAD * SEQ * 56) return;
    int m = i % 56; int t = i / 56;
    int n = t % SEQ; t /= SEQ;
    int h = t % NHEAD; int w = t / NHEAD;
    float v = -1e30f;
    if (m < SEQ)
        v = table[rel_index[n * SEQ + m] * NHEAD + h]
          + mask[((size_t)w * SEQ + n) * SEQ + m];
    g_bm[i] = v;
}

// ---------------------------------------------------------------------------
// tf32 HMMA GEMM: out[m][n] = sum_k A[m][k]*W[n][k] + bias[n]
//   Tile 128x96, BK=32, 256 thr = 8 warps (4M x 2N), warp tile 32x48.
//   cp.async (raw fp32) into 3-stage SMEM ring, ONE syncthreads per k-tile,
//   cvt.rna.tf32 applied AFTER fragment LDS (numerically identical).
//   GRID: blockIdx.x = N-tile (fast) so A-tile sharers are co-resident (L2).
//   PHASE1: A = x, O = g_qkv (scale q cols: n0 < 192). !PHASE1: A=g_attn, O=Oin.
// ---------------------------------------------------------------------------
#define ABUF 4608u             // 128*36 floats
#define BBUF 3456u             // 96*36 floats
#define STAGE (ABUF + BBUF)
#define GEMM_SMEM_FLOATS (3u*STAGE)    // 24192 floats = 96768 B

template<bool PHASE1>
__global__ void __launch_bounds__(256, 2)
gemm_mma(const float* __restrict__ Ain, const float* __restrict__ W,
         const float* __restrict__ bias, float* __restrict__ Oin,
         int Ncols, float qscale)
{
    extern __shared__ float sm[];
    __shared__ float bias_s[96];

    const float* A = PHASE1 ? Ain : g_attn;
    float*       O = PHASE1 ? g_qkv : Oin;

    const int tid  = threadIdx.x;
    const int wid  = tid >> 5;
    const int lane = tid & 31;
    const int gid  = lane >> 2;
    const int tig  = lane & 3;
    const size_t m0 = (size_t)blockIdx.y * 128;   // M-tile: slow-varying
    const int    n0 = blockIdx.x * 96;            // N-tile: fast-varying
    const int    wm = (wid >> 1) * 32;
    const int    wn = (wid & 1) * 48;

    if (tid < 24) ((float4*)bias_s)[tid] = ((const float4*)(bias + n0))[tid];

    // per-thread fixed coords for the copy (4 A rows + 3 B rows)
    const int ra = tid >> 3;            // A row for i=0 (stride 32 rows per i)
    const int qa = tid & 7;             // float4 column index
    const uint32_t smem_u32 = (uint32_t)__cvta_generic_to_shared(sm);

    auto cp_stage = [&](int kt, int buf) {
        const int k0 = kt * 32;
        const uint32_t sbase = smem_u32 + (uint32_t)(buf * STAGE) * 4u;
        #pragma unroll
        for (int i = 0; i < 4; ++i) {
            int r = ra + i * 32;
            cp16(sbase + (uint32_t)(r * 36 + qa * 4) * 4u,
                 A + (m0 + r) * (size_t)KD + k0 + qa * 4);
        }
        const uint32_t bbase = sbase + ABUF * 4u;
        #pragma unroll
        for (int i = 0; i < 3; ++i) {
            int r = ra + i * 32;
            cp16(bbase + (uint32_t)(r * 36 + qa * 4) * 4u,
                 W + (size_t)(n0 + r) * KD + k0 + qa * 4);
        }
        CP_COMMIT();
    };

    float acc[2][6][4] = {};

    // prologue: stage 0 and 1 in flight; wait for stage 0
    cp_stage(0, 0);
    cp_stage(1, 1);
    CP_WAIT(1);
    __syncthreads();

    #pragma unroll 1
    for (int kt = 0; kt < 6; ++kt) {
        const int buf = kt % 3;
        const float* As = sm + buf * STAGE;
        const float* Bs = As + ABUF;

        #pragma unroll
        for (int kk = 0; kk < 32; kk += 8) {
            uint32_t afr[2][4], bfr[6][2];
            #pragma unroll
            for (int mi = 0; mi < 2; ++mi) {
                int r = wm + mi * 16 + gid;
                afr[mi][0] = f2tf32(As[r * 36 + kk + tig]);
                afr[mi][1] = f2tf32(As[(r + 8) * 36 + kk + tig]);
                afr[mi][2] = f2tf32(As[r * 36 + kk + 4 + tig]);
                afr[mi][3] = f2tf32(As[(r + 8) * 36 + kk + 4 + tig]);
            }
            #pragma unroll
            for (int ni = 0; ni < 6; ++ni) {
                int r = wn + ni * 8 + gid;
                bfr[ni][0] = f2tf32(Bs[r * 36 + kk + tig]);
                bfr[ni][1] = f2tf32(Bs[r * 36 + kk + 4 + tig]);
            }
            #pragma unroll
            for (int mi = 0; mi < 2; ++mi)
                #pragma unroll
                for (int ni = 0; ni < 6; ++ni)
                    mma_tf32(acc[mi][ni], afr[mi], bfr[ni]);
        }

        // prefetch kt+2 into buf (kt+2)%3 == (kt-1)%3 (freed by last barrier)
        if (kt < 4) {
            cp_stage(kt + 2, (kt + 2) % 3);
            CP_WAIT(1);                  // stage kt+1 complete
        } else if (kt == 4) {
            CP_WAIT(0);                  // stage 5 complete
        }
        __syncthreads();
    }

    // ---- epilogue: stage to SMEM (stride 100), then coalesced STG ----
    float* stage = sm;
    #pragma unroll
    for (int mi = 0; mi < 2; ++mi) {
        int row0 = wm + mi * 16 + gid;
        #pragma unroll
        for (int ni = 0; ni < 6; ++ni) {
            int col0 = wn + ni * 8 + 2 * tig;
            *(float2*)(stage + row0 * 100 + col0)       = make_float2(acc[mi][ni][0], acc[mi][ni][1]);
            *(float2*)(stage + (row0 + 8) * 100 + col0) = make_float2(acc[mi][ni][2], acc[mi][ni][3]);
        }
    }
    __syncthreads();

    const bool doscale = PHASE1 && (n0 < CDIM);
    #pragma unroll
    for (int i = 0; i < 12; ++i) {
        int idx = tid + i * 256;
        int row = idx / 24, c4 = idx - row * 24;
        float4 v  = *(float4*)(stage + row * 100 + c4 * 4);
        float4 bv = *(float4*)(bias_s + c4 * 4);
        float4 o;
        o.x = v.x + bv.x; o.y = v.y + bv.y; o.z = v.z + bv.z; o.w = v.w + bv.w;
        if (doscale) { o.x *= qscale; o.y *= qscale; o.z *= qscale; o.w *= qscale; }
        *(float4*)(O + (m0 + row) * (size_t)Ncols + n0 + c4 * 4) = o;
    }
}

// ---------------------------------------------------------------------------
// K2: tensor-core attention. One block per (window, head), 128 thr / 4 warps.
// Warp w owns rows [w*16, w*16+16). 3xTF32 split MMAs for QK^T and P@V.
// Softmax in registers via quad shuffles; P fragments via intra-quad shfl.
// ---------------------------------------------------------------------------
#define QSTR 36
#define KSTR 36
#define VSTR 40
#define ATTN_SMEM_FLOATS (2*49*QSTR + 2*56*KSTR + 2*56*VSTR)   // 12040 -> 48160 B

__global__ void __launch_bounds__(128)
attn_mma()
{
    extern __shared__ float s[];
    float* qh = s;
    float* ql = qh + 49 * QSTR;
    float* kh = ql + 49 * QSTR;
    float* kl = kh + 56 * KSTR;
    float* vh = kl + 56 * KSTR;
    float* vl = vh + 56 * VSTR;

    const int b = blockIdx.x;
    const int h = blockIdx.y;
    const int tid = threadIdx.x;
    const float* base = g_qkv + (size_t)b * SEQ * QKV_COLS;

    for (int i = tid; i < 49 * 8; i += 128) {
        int n = i >> 3, c = (i & 7) * 4;
        float4 v = *(const float4*)(base + n * QKV_COLS + h * HDIM + c);
        float4 hi, lo;
        split2(v.x, hi.x, lo.x); split2(v.y, hi.y, lo.y);
        split2(v.z, hi.z, lo.z); split2(v.w, hi.w, lo.w);
        *(float4*)(qh + n * QSTR + c) = hi;
        *(float4*)(ql + n * QSTR + c) = lo;
    }
    for (int i = tid; i < 56 * 8; i += 128) {
        int n = i >> 3, c = (i & 7) * 4;
        float4 kv = make_float4(0.f, 0.f, 0.f, 0.f), vv = kv;
        if (n < SEQ) {
            const float* src = base + n * QKV_COLS + CDIM + h * HDIM + c;
            kv = *(const float4*)src;
            vv = *(const float4*)(src + CDIM);
        }
        float4 hi, lo;
        split2(kv.x, hi.x, lo.x); split2(kv.y, hi.y, lo.y);
        split2(kv.z, hi.z, lo.z); split2(kv.w, hi.w, lo.w);
        *(float4*)(kh + n * KSTR + c) = hi;
        *(float4*)(kl + n * KSTR + c) = lo;
        split2(vv.x, hi.x, lo.x); split2(vv.y, hi.y, lo.y);
        split2(vv.z, hi.z, lo.z); split2(vv.w, hi.w, lo.w);
        *(float4*)(vh + n * VSTR + c) = hi;
        *(float4*)(vl + n * VSTR + c) = lo;
    }
    __syncthreads();

    const int lane = tid & 31, w = tid >> 5;
    const int gid = lane >> 2, tig = lane & 3;
    const int row0 = w * 16 + gid, row1 = row0 + 8;
    const int r0c = min(row0, 48), r1c = min(row1, 48);

    float c[7][4] = {};
    #pragma unroll
    for (int ks = 0; ks < 4; ++ks) {
        const int dk = ks * 8;
        float a0h = qh[r0c * QSTR + dk + tig],     a0l = ql[r0c * QSTR + dk + tig];
        float a1h = qh[r1c * QSTR + dk + tig],     a1l = ql[r1c * QSTR + dk + tig];
        float a2h = qh[r0c * QSTR + dk + tig + 4], a2l = ql[r0c * QSTR + dk + tig + 4];
        float a3h = qh[r1c * QSTR + dk + tig + 4], a3l = ql[r1c * QSTR + dk + tig + 4];
        #pragma unroll
        for (int nt = 0; nt < 7; ++nt) {
            int kr = nt * 8 + gid;
            float b0h = kh[kr * KSTR + dk + tig],     b0l = kl[kr * KSTR + dk + tig];
            float b1h = kh[kr * KSTR + dk + tig + 4], b1l = kl[kr * KSTR + dk + tig + 4];
            mma_f(c[nt], a0h, a1h, a2h, a3h, b0h, b1h);
            mma_f(c[nt], a0h, a1h, a2h, a3h, b0l, b1l);
            mma_f(c[nt], a0l, a1l, a2l, a3l, b0h, b1h);
        }
    }

    const float* bmp = g_bm + ((size_t)((b & 63) * NHEAD + h)) * (SEQ * 56);
    #pragma unroll
    for (int nt = 0; nt < 7; ++nt) {
        float2 bm0 = *(const float2*)(bmp + r0c * 56 + nt * 8 + 2 * tig);
        float2 bm1 = *(const float2*)(bmp + r1c * 56 + nt * 8 + 2 * tig);
        c[nt][0] += bm0.x; c[nt][1] += bm0.y;
        c[nt][2] += bm1.x; c[nt][3] += bm1.y;
    }

    float mx0 = -1e30f, mx1 = -1e30f;
    #pragma unroll
    for (int nt = 0; nt < 7; ++nt) {
        mx0 = fmaxf(mx0, fmaxf(c[nt][0], c[nt][1]));
        mx1 = fmaxf(mx1, fmaxf(c[nt][2], c[nt][3]));
    }
    mx0 = fmaxf(mx0, __shfl_xor_sync(0xffffffffu, mx0, 1));
    mx0 = fmaxf(mx0, __shfl_xor_sync(0xffffffffu, mx0, 2));
    mx1 = fmaxf(mx1, __shfl_xor_sync(0xffffffffu, mx1, 1));
    mx1 = fmaxf(mx1, __shfl_xor_sync(0xffffffffu, mx1, 2));

    float s0 = 0.f, s1 = 0.f;
    #pragma unroll
    for (int nt = 0; nt < 7; ++nt) {
        c[nt][0] = __expf(c[nt][0] - mx0); s0 += c[nt][0];
        c[nt][1] = __expf(c[nt][1] - mx0); s0 += c[nt][1];
        c[nt][2] = __expf(c[nt][2] - mx1); s1 += c[nt][2];
        c[nt][3] = __expf(c[nt][3] - mx1); s1 += c[nt][3];
    }
    s0 += __shfl_xor_sync(0xffffffffu, s0, 1);
    s0 += __shfl_xor_sync(0xffffffffu, s0, 2);
    s1 += __shfl_xor_sync(0xffffffffu, s1, 1);
    s1 += __shfl_xor_sync(0xffffffffu, s1, 2);
    const float inv0 = 1.0f / s0, inv1 = 1.0f / s1;

    float o[4][4] = {};
    const int sA = (lane & ~3) | (tig >> 1);
    const int sB = sA + 2;
    const bool odd = tig & 1;
    #pragma unroll
    for (int j = 0; j < 7; ++j) {
        float t00 = __shfl_sync(0xffffffffu, c[j][0], sA);
        float t01 = __shfl_sync(0xffffffffu, c[j][1], sA);
        float t20 = __shfl_sync(0xffffffffu, c[j][0], sB);
        float t21 = __shfl_sync(0xffffffffu, c[j][1], sB);
        float t10 = __shfl_sync(0xffffffffu, c[j][2], sA);
        float t11 = __shfl_sync(0xffffffffu, c[j][3], sA);
        float t30 = __shfl_sync(0xffffffffu, c[j][2], sB);
        float t31 = __shfl_sync(0xffffffffu, c[j][3], sB);
        float a0 = odd ? t01 : t00;
        float a2 = odd ? t21 : t20;
        float a1 = odd ? t11 : t10;
        float a3 = odd ? t31 : t30;
        float a0h, a0l, a1h, a1l, a2h, a2l, a3h, a3l;
        split2(a0, a0h, a0l); split2(a1, a1h, a1l);
        split2(a2, a2h, a2l); split2(a3, a3h, a3l);
        const int vr0 = j * 8 + tig, vr1 = vr0 + 4;
        #pragma unroll
        for (int nd = 0; nd < 4; ++nd) {
            int col = nd * 8 + gid;
            float b0h = vh[vr0 * VSTR + col], b0l = vl[vr0 * VSTR + col];
            float b1h = vh[vr1 * VSTR + col], b1l = vl[vr1 * VSTR + col];
            mma_f(o[nd], a0h, a1h, a2h, a3h, b0h, b1h);
            mma_f(o[nd], a0h, a1h, a2h, a3h, b0l, b1l);
            mma_f(o[nd], a0l, a1l, a2l, a3l, b0h, b1h);
        }
    }

    float* ob = g_attn + (size_t)b * SEQ * CDIM + h * HDIM;
    if (row0 < SEQ) {
        #pragma unroll
        for (int nd = 0; nd < 4; ++nd)
            *(float2*)(ob + row0 * CDIM + nd * 8 + 2 * tig) =
                make_float2(o[nd][0] * inv0, o[nd][1] * inv0);
    }
    if (row1 < SEQ) {
        #pragma unroll
        for (int nd = 0; nd < 4; ++nd)
            *(float2*)(ob + row1 * CDIM + nd * 8 + 2 * tig) =
                make_float2(o[nd][2] * inv1, o[nd][3] * inv1);
    }
}

// ---------------------------------------------------------------------------
extern "C" void kernel_launch(void* const* d_in, const int* in_sizes, int n_in,
                              void* d_out, int out_size)
{
    const float* x     = (const float*)d_in[0];
    const float* mask  = (const float*)d_in[1];
    const float* table = (const float*)d_in[2];
    const float* qkvw  = (const float*)d_in[3];
    const float* qkvb  = (const float*)d_in[4];
    const float* projw = (const float*)d_in[5];
    const float* projb = (const float*)d_in[6];
    const int*   relix = (const int*)d_in[7];
    float* out = (float*)d_out;

    const float qscale = 0.17677669529663687f;  // 1/sqrt(32)
    const int gemm_smem = GEMM_SMEM_FLOATS * 4;
    const int attn_smem = ATTN_SMEM_FLOATS * 4;

    cudaFuncSetAttribute((void*)gemm_mma<true>,
                         cudaFuncAttributeMaxDynamicSharedMemorySize, gemm_smem);
    cudaFuncSetAttribute((void*)gemm_mma<false>,
                         cudaFuncAttributeMaxDynamicSharedMemorySize, gemm_smem);
    cudaFuncSetAttribute((void*)attn_mma,
                         cudaFuncAttributeMaxDynamicSharedMemorySize, attn_smem);

    bm_kernel<<<(64 * NHEAD * SEQ * 56 + 255) / 256, 256>>>(table, mask, relix);

    // QKV: M=200704, N=576. N-tile fast-varying -> A-tile sharers co-resident.
    gemm_mma<true><<<dim3(6, MROWS / 128), 256, gemm_smem>>>(
        x, qkvw, qkvb, nullptr, QKV_COLS, qscale);

    attn_mma<<<dim3(B_WIN, NHEAD), 128, attn_smem>>>();

    // Proj: M=200704, N=192. Same N-fast ordering.
    gemm_mma<false><<<dim3(2, MROWS / 128), 256, gemm_smem>>>(
        nullptr, projw, projb, out, CDIM, 1.0f);
}

// round 10
// speedup vs baseline: 1.4874x; 1.2703x over previous
#include <cuda_runtime.h>
#include <cstdint>

// ---------------- problem constants ----------------
#define B_WIN    4096
#define SEQ      49
#define CDIM     192
#define NHEAD    6
#define HDIM     32
#define KD       192
#define QKV_COLS 576
#define MROWS    200704       // B_WIN * SEQ

// ---------------- scratch (__device__ globals, allocation-free) -------------
__device__ float g_qkv [(size_t)B_WIN * SEQ * QKV_COLS];
__device__ float g_attn[(size_t)B_WIN * SEQ * CDIM];
__device__ float g_bm  [64 * NHEAD * SEQ * 56];   // fused bias+mask, cols padded to 56

__device__ __forceinline__ uint32_t f2tf32(float x) {
    uint32_t r; asm("cvt.rna.tf32.f32 %0, %1;" : "=r"(r) : "f"(x)); return r;
}

__device__ __forceinline__ void mma_tf32(float* d, const uint32_t* a, const uint32_t* b) {
    asm volatile(
        "mma.sync.aligned.m16n8k8.row.col.f32.tf32.tf32.f32 "
        "{%0,%1,%2,%3}, {%4,%5,%6,%7}, {%8,%9}, {%0,%1,%2,%3};"
        : "+f"(d[0]), "+f"(d[1]), "+f"(d[2]), "+f"(d[3])
        : "r"(a[0]), "r"(a[1]), "r"(a[2]), "r"(a[3]), "r"(b[0]), "r"(b[1]));
}
__device__ __forceinline__ void mma_f(float* d, float a0, float a1, float a2, float a3,
                                      float b0, float b1) {
    asm volatile(
        "mma.sync.aligned.m16n8k8.row.col.f32.tf32.tf32.f32 "
        "{%0,%1,%2,%3}, {%4,%5,%6,%7}, {%8,%9}, {%0,%1,%2,%3};"
        : "+f"(d[0]), "+f"(d[1]), "+f"(d[2]), "+f"(d[3])
        : "r"(__float_as_uint(a0)), "r"(__float_as_uint(a1)),
          "r"(__float_as_uint(a2)), "r"(__float_as_uint(a3)),
          "r"(__float_as_uint(b0)), "r"(__float_as_uint(b1)));
}

__device__ __forceinline__ void cp16(uint32_t smem_addr, const void* gptr) {
    asm volatile("cp.async.cg.shared.global [%0], [%1], 16;"
                 :: "r"(smem_addr), "l"(gptr) : "memory");
}
#define CP_COMMIT() asm volatile("cp.async.commit_group;" ::: "memory")
#define CP_WAIT(n)  asm volatile("cp.async.wait_group %0;" :: "n"(n) : "memory")

// ---------------------------------------------------------------------------
// K0: fused bias+mask table: g_bm[w][h][n][m] (m padded to 56 with -1e30)
// ---------------------------------------------------------------------------
__global__ void bm_kernel(const float* __restrict__ table,
                          const float* __restrict__ mask,
                          const int* __restrict__ rel_index)
{
    int i = blockIdx.x * blockDim.x + threadIdx.x;
    if (i >= 64 * NHEAD * SEQ * 56) return;
    int m = i % 56; int t = i / 56;
    int n = t % SEQ; t /= SEQ;
    int h = t % NHEAD; int w = t / NHEAD;
    float v = -1e30f;
    if (m < SEQ)
        v = table[rel_index[n * SEQ + m] * NHEAD + h]
          + mask[((size_t)w * SEQ + n) * SEQ + m];
    g_bm[i] = v;
}

// ---------------------------------------------------------------------------
// tf32 HMMA GEMM (R9, unchanged): cp.async 3-stage ring, one barrier/k-tile.
// ---------------------------------------------------------------------------
#define ABUF 4608u             // 128*36 floats
#define BBUF 3456u             // 96*36 floats
#define STAGE (ABUF + BBUF)
#define GEMM_SMEM_FLOATS (3u*STAGE)    // 24192 floats = 96768 B

template<bool PHASE1>
__global__ void __launch_bounds__(256, 2)
gemm_mma(const float* __restrict__ Ain, const float* __restrict__ W,
         const float* __restrict__ bias, float* __restrict__ Oin,
         int Ncols, float qscale)
{
    extern __shared__ float sm[];
    __shared__ float bias_s[96];

    const float* A = PHASE1 ? Ain : g_attn;
    float*       O = PHASE1 ? g_qkv : Oin;

    const int tid  = threadIdx.x;
    const int wid  = tid >> 5;
    const int lane = tid & 31;
    const int gid  = lane >> 2;
    const int tig  = lane & 3;
    const size_t m0 = (size_t)blockIdx.y * 128;   // M-tile: slow-varying
    const int    n0 = blockIdx.x * 96;            // N-tile: fast-varying
    const int    wm = (wid >> 1) * 32;
    const int    wn = (wid & 1) * 48;

    if (tid < 24) ((float4*)bias_s)[tid] = ((const float4*)(bias + n0))[tid];

    const int ra = tid >> 3;
    const int qa = tid & 7;
    const uint32_t smem_u32 = (uint32_t)__cvta_generic_to_shared(sm);

    auto cp_stage = [&](int kt, int buf) {
        const int k0 = kt * 32;
        const uint32_t sbase = smem_u32 + (uint32_t)(buf * STAGE) * 4u;
        #pragma unroll
        for (int i = 0; i < 4; ++i) {
            int r = ra + i * 32;
            cp16(sbase + (uint32_t)(r * 36 + qa * 4) * 4u,
                 A + (m0 + r) * (size_t)KD + k0 + qa * 4);
        }
        const uint32_t bbase = sbase + ABUF * 4u;
        #pragma unroll
        for (int i = 0; i < 3; ++i) {
            int r = ra + i * 32;
            cp16(bbase + (uint32_t)(r * 36 + qa * 4) * 4u,
                 W + (size_t)(n0 + r) * KD + k0 + qa * 4);
        }
        CP_COMMIT();
    };

    float acc[2][6][4] = {};

    cp_stage(0, 0);
    cp_stage(1, 1);
    CP_WAIT(1);
    __syncthreads();

    #pragma unroll 1
    for (int kt = 0; kt < 6; ++kt) {
        const int buf = kt % 3;
        const float* As = sm + buf * STAGE;
        const float* Bs = As + ABUF;

        #pragma unroll
        for (int kk = 0; kk < 32; kk += 8) {
            uint32_t afr[2][4], bfr[6][2];
            #pragma unroll
            for (int mi = 0; mi < 2; ++mi) {
                int r = wm + mi * 16 + gid;
                afr[mi][0] = f2tf32(As[r * 36 + kk + tig]);
                afr[mi][1] = f2tf32(As[(r + 8) * 36 + kk + tig]);
                afr[mi][2] = f2tf32(As[r * 36 + kk + 4 + tig]);
                afr[mi][3] = f2tf32(As[(r + 8) * 36 + kk + 4 + tig]);
            }
            #pragma unroll
            for (int ni = 0; ni < 6; ++ni) {
                int r = wn + ni * 8 + gid;
                bfr[ni][0] = f2tf32(Bs[r * 36 + kk + tig]);
                bfr[ni][1] = f2tf32(Bs[r * 36 + kk + 4 + tig]);
            }
            #pragma unroll
            for (int mi = 0; mi < 2; ++mi)
                #pragma unroll
                for (int ni = 0; ni < 6; ++ni)
                    mma_tf32(acc[mi][ni], afr[mi], bfr[ni]);
        }

        if (kt < 4) {
            cp_stage(kt + 2, (kt + 2) % 3);
            CP_WAIT(1);
        } else if (kt == 4) {
            CP_WAIT(0);
        }
        __syncthreads();
    }

    // ---- epilogue: stage to SMEM (stride 100), then coalesced STG ----
    float* stage = sm;
    #pragma unroll
    for (int mi = 0; mi < 2; ++mi) {
        int row0 = wm + mi * 16 + gid;
        #pragma unroll
        for (int ni = 0; ni < 6; ++ni) {
            int col0 = wn + ni * 8 + 2 * tig;
            *(float2*)(stage + row0 * 100 + col0)       = make_float2(acc[mi][ni][0], acc[mi][ni][1]);
            *(float2*)(stage + (row0 + 8) * 100 + col0) = make_float2(acc[mi][ni][2], acc[mi][ni][3]);
        }
    }
    __syncthreads();

    const bool doscale = PHASE1 && (n0 < CDIM);
    #pragma unroll
    for (int i = 0; i < 12; ++i) {
        int idx = tid + i * 256;
        int row = idx / 24, c4 = idx - row * 24;
        float4 v  = *(float4*)(stage + row * 100 + c4 * 4);
        float4 bv = *(float4*)(bias_s + c4 * 4);
        float4 o;
        o.x = v.x + bv.x; o.y = v.y + bv.y; o.z = v.z + bv.z; o.w = v.w + bv.w;
        if (doscale) { o.x *= qscale; o.y *= qscale; o.z *= qscale; o.w *= qscale; }
        *(float4*)(O + (m0 + row) * (size_t)Ncols + n0 + c4 * 4) = o;
    }
}

// ---------------------------------------------------------------------------
// K2: tensor-core attention, PLAIN single-pass tf32 (no 3x split).
// One block per (window, head), 128 thr / 4 warps; warp w owns rows [16w,16w+16).
// q/k/v stored PRE-ROUNDED to tf32 in SMEM -> QK inner loop is pure LDS+MMA.
// Softmax in registers (quad shuffles); P fragments via intra-quad shfl + cvt.
// ---------------------------------------------------------------------------
#define QSTR 36
#define KSTR 36
#define VSTR 40
#define ATTN_SMEM_FLOATS (49*QSTR + 56*KSTR + 56*VSTR)   // 6020 -> 24080 B

__global__ void __launch_bounds__(128)
attn_mma()
{
    extern __shared__ float s[];
    float* qs = s;
    float* ks = qs + 49 * QSTR;
    float* vs = ks + 56 * KSTR;

    const int b = blockIdx.x;
    const int h = blockIdx.y;
    const int tid = threadIdx.x;
    const float* base = g_qkv + (size_t)b * SEQ * QKV_COLS;

    // ---- load q (49x32), k/v (56x32 zero-padded); round to tf32 at store ----
    for (int i = tid; i < 49 * 8; i += 128) {
        int n = i >> 3, c = (i & 7) * 4;
        float4 v = *(const float4*)(base + n * QKV_COLS + h * HDIM + c);
        uint4 t = make_uint4(f2tf32(v.x), f2tf32(v.y), f2tf32(v.z), f2tf32(v.w));
        *(uint4*)(qs + n * QSTR + c) = t;
    }
    for (int i = tid; i < 56 * 8; i += 128) {
        int n = i >> 3, c = (i & 7) * 4;
        float4 kv = make_float4(0.f, 0.f, 0.f, 0.f), vv = kv;
        if (n < SEQ) {
            const float* src = base + n * QKV_COLS + CDIM + h * HDIM + c;
            kv = *(const float4*)src;
            vv = *(const float4*)(src + CDIM);
        }
        *(uint4*)(ks + n * KSTR + c) =
            make_uint4(f2tf32(kv.x), f2tf32(kv.y), f2tf32(kv.z), f2tf32(kv.w));
        *(uint4*)(vs + n * VSTR + c) =
            make_uint4(f2tf32(vv.x), f2tf32(vv.y), f2tf32(vv.z), f2tf32(vv.w));
    }
    __syncthreads();

    const int lane = tid & 31, w = tid >> 5;
    const int gid = lane >> 2, tig = lane & 3;
    const int row0 = w * 16 + gid, row1 = row0 + 8;
    const int r0c = min(row0, 48), r1c = min(row1, 48);

    // ---- S = Q K^T (plain tf32) ----
    float c[7][4] = {};
    #pragma unroll
    for (int kk = 0; kk < 4; ++kk) {
        const int dk = kk * 8;
        float a0 = qs[r0c * QSTR + dk + tig];
        float a1 = qs[r1c * QSTR + dk + tig];
        float a2 = qs[r0c * QSTR + dk + tig + 4];
        float a3 = qs[r1c * QSTR + dk + tig + 4];
        #pragma unroll
        for (int nt = 0; nt < 7; ++nt) {
            int kr = nt * 8 + gid;
            mma_f(c[nt], a0, a1, a2, a3,
                  ks[kr * KSTR + dk + tig], ks[kr * KSTR + dk + tig + 4]);
        }
    }

    // ---- add fused bias+mask ----
    const float* bmp = g_bm + ((size_t)((b & 63) * NHEAD + h)) * (SEQ * 56);
    #pragma unroll
    for (int nt = 0; nt < 7; ++nt) {
        float2 bm0 = *(const float2*)(bmp + r0c * 56 + nt * 8 + 2 * tig);
        float2 bm1 = *(const float2*)(bmp + r1c * 56 + nt * 8 + 2 * tig);
        c[nt][0] += bm0.x; c[nt][1] += bm0.y;
        c[nt][2] += bm1.x; c[nt][3] += bm1.y;
    }

    // ---- softmax (per-row, quad shuffles) ----
    float mx0 = -1e30f, mx1 = -1e30f;
    #pragma unroll
    for (int nt = 0; nt < 7; ++nt) {
        mx0 = fmaxf(mx0, fmaxf(c[nt][0], c[nt][1]));
        mx1 = fmaxf(mx1, fmaxf(c[nt][2], c[nt][3]));
    }
    mx0 = fmaxf(mx0, __shfl_xor_sync(0xffffffffu, mx0, 1));
    mx0 = fmaxf(mx0, __shfl_xor_sync(0xffffffffu, mx0, 2));
    mx1 = fmaxf(mx1, __shfl_xor_sync(0xffffffffu, mx1, 1));
    mx1 = fmaxf(mx1, __shfl_xor_sync(0xffffffffu, mx1, 2));

    float s0 = 0.f, s1 = 0.f;
    #pragma unroll
    for (int nt = 0; nt < 7; ++nt) {
        c[nt][0] = __expf(c[nt][0] - mx0); s0 += c[nt][0];
        c[nt][1] = __expf(c[nt][1] - mx0); s0 += c[nt][1];
        c[nt][2] = __expf(c[nt][2] - mx1); s1 += c[nt][2];
        c[nt][3] = __expf(c[nt][3] - mx1); s1 += c[nt][3];
    }
    s0 += __shfl_xor_sync(0xffffffffu, s0, 1);
    s0 += __shfl_xor_sync(0xffffffffu, s0, 2);
    s1 += __shfl_xor_sync(0xffffffffu, s1, 1);
    s1 += __shfl_xor_sync(0xffffffffu, s1, 2);
    const float inv0 = 1.0f / s0, inv1 = 1.0f / s1;

    // ---- O = P V (plain tf32); P fragments via intra-quad shfl ----
    float o[4][4] = {};
    const int sA = (lane & ~3) | (tig >> 1);
    const int sB = sA + 2;
    const bool odd = tig & 1;
    #pragma unroll
    for (int j = 0; j < 7; ++j) {
        float t00 = __shfl_sync(0xffffffffu, c[j][0], sA);
        float t01 = __shfl_sync(0xffffffffu, c[j][1], sA);
        float t20 = __shfl_sync(0xffffffffu, c[j][0], sB);
        float t21 = __shfl_sync(0xffffffffu, c[j][1], sB);
        float t10 = __shfl_sync(0xffffffffu, c[j][2], sA);
        float t11 = __shfl_sync(0xffffffffu, c[j][3], sA);
        float t30 = __shfl_sync(0xffffffffu, c[j][2], sB);
        float t31 = __shfl_sync(0xffffffffu, c[j][3], sB);
        float a0 = __uint_as_float(f2tf32(odd ? t01 : t00));
        float a1 = __uint_as_float(f2tf32(odd ? t11 : t10));
        float a2 = __uint_as_float(f2tf32(odd ? t21 : t20));
        float a3 = __uint_as_float(f2tf32(odd ? t31 : t30));
        const int vr0 = j * 8 + tig, vr1 = vr0 + 4;
        #pragma unroll
        for (int nd = 0; nd < 4; ++nd) {
            int col = nd * 8 + gid;
            mma_f(o[nd], a0, a1, a2, a3,
                  vs[vr0 * VSTR + col], vs[vr1 * VSTR + col]);
        }
    }

    // ---- write O (rows < 49 only), scaled by 1/rowsum ----
    float* ob = g_attn + (size_t)b * SEQ * CDIM + h * HDIM;
    if (row0 < SEQ) {
        #pragma unroll
        for (int nd = 0; nd < 4; ++nd)
            *(float2*)(ob + row0 * CDIM + nd * 8 + 2 * tig) =
                make_float2(o[nd][0] * inv0, o[nd][1] * inv0);
    }
    if (row1 < SEQ) {
        #pragma unroll
        for (int nd = 0; nd < 4; ++nd)
            *(float2*)(ob + row1 * CDIM + nd * 8 + 2 * tig) =
                make_float2(o[nd][2] * inv1, o[nd][3] * inv1);
    }
}

// ---------------------------------------------------------------------------
extern "C" void kernel_launch(void* const* d_in, const int* in_sizes, int n_in,
                              void* d_out, int out_size)
{
    const float* x     = (const float*)d_in[0];
    const float* mask  = (const float*)d_in[1];
    const float* table = (const float*)d_in[2];
    const float* qkvw  = (const float*)d_in[3];
    const float* qkvb  = (const float*)d_in[4];
    const float* projw = (const float*)d_in[5];
    const float* projb = (const float*)d_in[6];
    const int*   relix = (const int*)d_in[7];
    float* out = (float*)d_out;

    const float qscale = 0.17677669529663687f;  // 1/sqrt(32)
    const int gemm_smem = GEMM_SMEM_FLOATS * 4;
    const int attn_smem = ATTN_SMEM_FLOATS * 4;

    cudaFuncSetAttribute((void*)gemm_mma<true>,
                         cudaFuncAttributeMaxDynamicSharedMemorySize, gemm_smem);
    cudaFuncSetAttribute((void*)gemm_mma<false>,
                         cudaFuncAttributeMaxDynamicSharedMemorySize, gemm_smem);
    cudaFuncSetAttribute((void*)attn_mma,
                         cudaFuncAttributeMaxDynamicSharedMemorySize, attn_smem);

    bm_kernel<<<(64 * NHEAD * SEQ * 56 + 255) / 256, 256>>>(table, mask, relix);

    // QKV: M=200704, N=576. N-tile fast-varying -> A-tile sharers co-resident.
    gemm_mma<true><<<dim3(6, MROWS / 128), 256, gemm_smem>>>(
        x, qkvw, qkvb, nullptr, QKV_COLS, qscale);

    attn_mma<<<dim3(B_WIN, NHEAD), 128, attn_smem>>>();

    // Proj: M=200704, N=192. Same N-fast ordering.
    gemm_mma<false><<<dim3(2, MROWS / 128), 256, gemm_smem>>>(
        nullptr, projw, projb, out, CDIM, 1.0f);
}